// round 11
// baseline (speedup 1.0000x reference)
#include <cuda_runtime.h>
#include <math.h>

// ---------------- problem constants ----------------
#define NTAU 64
#define NANG 64
#define NAP  68              // NANG + KW-1 circular pad
#define IC   8
#define OC   32
#define KH   5
#define KW   5
#define HOUT 60              // NTAU - KH + 1
#define HA   32              // half 0: rows 0..31  (256 tasks = 8 even passes)
#define HB   28              // half 1: rows 32..59 (224 tasks = 7 even passes)
#define XROWS_MAX 36         // HA + KH - 1
#define NSAMP 1024           // 4 * 16 * 16
#define XMAX_ELEMS (IC*XROWS_MAX*NAP)     // 19584 floats worst-case half tile
#define WELEMS (IC*KH*KW*OC)              // 6400

typedef unsigned long long u64;

// ---------------- device scratch (no allocations allowed) ----------------
__device__ float g_w[WELEMS];                // normalized weights [c][kh][kw][oc]
__device__ u64   g_key[2 * NSAMP * OC];      // per-half ordered argmax keys

// ---------------- packed f32x2 helpers (Blackwell FFMA2) ----------------
__device__ __forceinline__ u64 pack_dup(float v) {
    u64 r; asm("mov.b64 %0, {%1, %1};" : "=l"(r) : "f"(v)); return r;
}
__device__ __forceinline__ void unpack2(u64 v, float& lo, float& hi) {
    asm("mov.b64 {%0, %1}, %2;" : "=f"(lo), "=f"(hi) : "l"(v));
}
__device__ __forceinline__ u64 ffma2(u64 a, u64 b, u64 c) {
    u64 d; asm("fma.rn.f32x2 %0, %1, %2, %3;" : "=l"(d) : "l"(a), "l"(b), "l"(c));
    return d;
}

// ---------------- cp.async helpers ----------------
__device__ __forceinline__ unsigned smem_u32(const void* p) {
    return (unsigned)__cvta_generic_to_shared(p);
}
__device__ __forceinline__ void cp_async16(unsigned saddr, const void* gaddr) {
    asm volatile("cp.async.cg.shared.global [%0], [%1], 16;"
                 :: "r"(saddr), "l"(gaddr) : "memory");
}
__device__ __forceinline__ void cp_async4(unsigned saddr, const void* gaddr) {
    asm volatile("cp.async.ca.shared.global [%0], [%1], 4;"
                 :: "r"(saddr), "l"(gaddr) : "memory");
}
__device__ __forceinline__ void cp_async_commit_wait() {
    asm volatile("cp.async.commit_group;\n\tcp.async.wait_group 0;" ::: "memory");
}

// ---------------- weight normalization ----------------
__global__ void prep_weights_kernel(const float* __restrict__ v,
                                    const float* __restrict__ g) {
    int oc = threadIdx.x;
    if (oc >= OC) return;
    const float* vp = v + oc * (IC*KH*KW);
    float s = 0.0f;
    for (int i = 0; i < IC*KH*KW; i++) { float t = vp[i]; s += t * t; }
    float scale = g[oc] / sqrtf(s);
    for (int c = 0; c < IC; c++)
        for (int kh = 0; kh < KH; kh++)
            for (int kw = 0; kw < KW; kw++)
                g_w[((c*KH + kh)*KW + kw)*OC + oc] =
                    vp[(c*KH + kh)*KW + kw] * scale;
}

// ---------------- conv + per-(n,oc,half) max/argmax ----------------
// grid = (1024, 2): one (sample, h-half) per CTA; block = 256
// Loads x DIRECTLY from (B,C,T,A,16,16) layout via 4B cp.async (no transpose).
// dyn smem <= (XMAX_ELEMS + WELEMS)*4 = 101.5 KB -> 2 CTAs/SM, 16 warps/SM
__global__ void __launch_bounds__(256, 2) conv_kernel(const float* __restrict__ x) {
    extern __shared__ float smem[];
    float* sx = smem;                    // [IC][xrows][NAP]
    __shared__ u64 best[OC];

    int n      = blockIdx.x;
    int half   = blockIdx.y;
    int h0     = half ? HA : 0;
    int hcount = half ? HB : HA;         // 28 or 32
    int xrows  = hcount + KH - 1;        // 32 or 36
    int tid    = threadIdx.x;

    float* sw = smem + IC * xrows * NAP; // [c][kh][kw][oc]

    // direct strided async loads from x: element (c,t,a) for this (b,p)
    // src = x[((b*8+c)*64 + (h0+t))*64 + (a&63)]*256 + p
    {
        int b = n >> 8, p = n & 255;
        const float* xb = x + ((size_t)b * IC * NTAU * NANG * 256) + p;
        int plane = xrows * NAP;         // floats per channel slab in smem
        #pragma unroll 1
        for (int i = tid; i < plane; i += 256) {
            int t = i / NAP;
            int a = i - t * NAP;
            int asrc = a & 63;           // circular wrap for a >= 64
            size_t goff = ((size_t)(h0 + t) * NANG + asrc) * 256;
            #pragma unroll
            for (int c = 0; c < IC; c++)
                cp_async4(smem_u32(sx + c * plane + i),
                          xb + (size_t)c * (NTAU * NANG * 256) + goff);
        }
        const float4* w4 = (const float4*)g_w;
        #pragma unroll 1
        for (int i = tid; i < WELEMS / 4; i += 256)
            cp_async16(smem_u32((float4*)sw + i), w4 + i);
        if (tid < OC) best[tid] = 0ull;
        cp_async_commit_wait();
    }
    __syncthreads();

    int warp   = tid >> 5;       // 0..7, owns 4 ocs
    int ocbase = warp * 4;
    int lane   = tid & 31;

    u64 lb[4];
    #pragma unroll
    for (int i = 0; i < 4; i++) lb[i] = 0ull;

    // tasks: hcount*8 (256 or 224) -> exactly 8 or 7 full passes per lane
    for (int task = lane; task < hcount * 8; task += 32) {
        int lh = task >> 3;
        int wg = task & 7;

        // acc[j][ww]: packed pair (oc = ocbase + 2j, 2j+1) at output col wg*8+ww
        u64 acc[2][8];
        #pragma unroll
        for (int j = 0; j < 2; j++)
            #pragma unroll
            for (int ww = 0; ww < 8; ww++) acc[j][ww] = 0ull;

        #pragma unroll 1
        for (int c = 0; c < IC; c++) {
            const float* xc = sx + (c * xrows + lh) * NAP + wg * 8;
            const u64*   wc = (const u64*)(sw + c * KH * KW * OC + ocbase);
            #pragma unroll
            for (int kh = 0; kh < KH; kh++) {
                const float* xr = xc + kh * NAP;
                float4 x0 = *(const float4*)(xr);
                float4 x1 = *(const float4*)(xr + 4);
                float4 x2 = *(const float4*)(xr + 8);
                float xv[12] = {x0.x,x0.y,x0.z,x0.w, x1.x,x1.y,x1.z,x1.w,
                                x2.x,x2.y,x2.z,x2.w};
                u64 xp[12];
                #pragma unroll
                for (int k = 0; k < 12; k++) xp[k] = pack_dup(xv[k]);

                const u64* wr = wc + kh * (KW * OC / 2);
                #pragma unroll
                for (int kw = 0; kw < KW; kw++) {
                    u64 w0 = wr[kw * 16 + 0];
                    u64 w1 = wr[kw * 16 + 1];
                    #pragma unroll
                    for (int ww = 0; ww < 8; ww++) {
                        u64 xb = xp[ww + kw];
                        acc[0][ww] = ffma2(w0, xb, acc[0][ww]);
                        acc[1][ww] = ffma2(w1, xb, acc[1][ww]);
                    }
                }
            }
        }

        // fold into ordered-key argmax (tie-break: smaller flat index wins)
        int hglob = h0 + lh;
        #pragma unroll
        for (int j = 0; j < 2; j++) {
            #pragma unroll
            for (int ww = 0; ww < 8; ww++) {
                float v0, v1;
                unpack2(acc[j][ww], v0, v1);
                int idx = hglob * NANG + wg * 8 + ww;
                unsigned ir = 0xFFFFFFFFu - (unsigned)idx;
                unsigned a0 = __float_as_uint(v0);
                a0 = (a0 & 0x80000000u) ? ~a0 : (a0 | 0x80000000u);
                u64 k0 = ((u64)a0 << 32) | ir;
                if (k0 > lb[2*j])   lb[2*j]   = k0;
                unsigned a1 = __float_as_uint(v1);
                a1 = (a1 & 0x80000000u) ? ~a1 : (a1 | 0x80000000u);
                u64 k1 = ((u64)a1 << 32) | ir;
                if (k1 > lb[2*j+1]) lb[2*j+1] = k1;
            }
        }
    }

    // warp-level max-reduce (all lanes share the same 4 ocs), lane 0 stores
    #pragma unroll
    for (int i = 0; i < 4; i++) {
        #pragma unroll
        for (int o = 16; o > 0; o >>= 1) {
            u64 other = __shfl_down_sync(0xFFFFFFFFu, lb[i], o);
            if (other > lb[i]) lb[i] = other;
        }
    }
    if (lane == 0) {
        #pragma unroll
        for (int i = 0; i < 4; i++) best[ocbase + i] = lb[i];
    }
    __syncthreads();

    if (tid < OC)
        g_key[(size_t)half * (NSAMP * OC) + n * OC + tid] = best[tid];
}

// ---------------- block reductions (256 threads) ----------------
__device__ __forceinline__ float blk_sum(float v, float* sbuf) {
    #pragma unroll
    for (int o = 16; o > 0; o >>= 1) v += __shfl_down_sync(0xFFFFFFFFu, v, o);
    int w = threadIdx.x >> 5, l = threadIdx.x & 31;
    if (l == 0) sbuf[w] = v;
    __syncthreads();
    if (w == 0) {
        float t = (l < 8) ? sbuf[l] : 0.0f;
        #pragma unroll
        for (int o = 4; o > 0; o >>= 1) t += __shfl_down_sync(0xFFFFFFFFu, t, o);
        if (l == 0) sbuf[8] = t;
    }
    __syncthreads();
    float r = sbuf[8];
    __syncthreads();
    return r;
}

__device__ __forceinline__ float blk_max(float v, float* sbuf) {
    #pragma unroll
    for (int o = 16; o > 0; o >>= 1)
        v = fmaxf(v, __shfl_down_sync(0xFFFFFFFFu, v, o));
    int w = threadIdx.x >> 5, l = threadIdx.x & 31;
    if (l == 0) sbuf[w] = v;
    __syncthreads();
    if (w == 0) {
        float t = (l < 8) ? sbuf[l] : -3.4e38f;
        #pragma unroll
        for (int o = 4; o > 0; o >>= 1)
            t = fmaxf(t, __shfl_down_sync(0xFFFFFFFFu, t, o));
        if (l == 0) sbuf[8] = t;
    }
    __syncthreads();
    float r = sbuf[8];
    __syncthreads();
    return r;
}

// ---------------- merge halves + softmax over spatial + phase encoding ----------------
// grid = (OC, 4), block = 256 (one thread per spatial position)
__global__ void finalize_kernel(float* __restrict__ out) {
    __shared__ float sbuf[9];
    int oc = blockIdx.x;
    int b  = blockIdx.y;
    int p  = threadIdx.x;
    int n  = b * 256 + p;

    u64 k0 = g_key[n * OC + oc];
    u64 k1 = g_key[(size_t)NSAMP * OC + n * OC + oc];
    u64 k  = (k1 > k0) ? k1 : k0;

    unsigned u = (unsigned)(k >> 32);
    unsigned bits = (u & 0x80000000u) ? (u ^ 0x80000000u) : ~u;
    float v  = __uint_as_float(bits);
    int   id = (int)(0xFFFFFFFFu - (unsigned)(k & 0xFFFFFFFFu));

    float m = blk_max(v, sbuf);
    float e = expf(v - m);
    float s = blk_sum(e, sbuf);
    float w = e / s;

    float tau = ((float)id / 64.0f) / 64.0f;      // (idx / NA) / NT, true division
    float mt  = blk_sum(w * tau, sbuf);

    float th = (float)(id & 63);
    float ph = (6.28318530717958647692f * th) / 64.0f;
    float mc = blk_sum(w * cosf(ph), sbuf);
    float ms = blk_sum(w * sinf(ph), sbuf);
    float ang = atan2f(ms, mc);
    float rel = ph - ang;

    int base = (b * 256 + p) * (4 * OC);
    out[base + oc]          = v;
    out[base + OC + oc]     = tau - mt;
    out[base + 2*OC + oc]   = cosf(rel);
    out[base + 3*OC + oc]   = sinf(rel);
}

// ---------------- launch ----------------
extern "C" void kernel_launch(void* const* d_in, const int* in_sizes, int n_in,
                              void* d_out, int out_size) {
    const float* x  = (const float*)d_in[0];   // (4,8,64,64,16,16)
    const float* cv = (const float*)d_in[1];   // (32,8,5,5)
    const float* cg = (const float*)d_in[2];   // (32,)
    float* out = (float*)d_out;                // (4,16,16,128,1,1)

    cudaFuncSetAttribute(conv_kernel,
                         cudaFuncAttributeMaxDynamicSharedMemorySize,
                         (XMAX_ELEMS + WELEMS) * 4);

    prep_weights_kernel<<<1, 32>>>(cv, cg);
    dim3 cg2(NSAMP, 2);
    conv_kernel<<<cg2, 256, (XMAX_ELEMS + WELEMS) * 4>>>(x);
    dim3 fg(OC, 4);
    finalize_kernel<<<fg, 256>>>(out);
}

// round 13
// speedup vs baseline: 1.2040x; 1.2040x over previous
#include <cuda_runtime.h>
#include <math.h>

// ---------------- problem constants ----------------
#define NTAU 64
#define NANG 64
#define NAP  68              // NANG + KW-1 circular pad
#define IC   8
#define OC   32
#define KH   5
#define KW   5
#define HOUT 60              // NTAU - KH + 1
#define HA   32              // half 0: rows 0..31  (256 tasks = 8 even passes)
#define HB   28              // half 1: rows 32..59 (224 tasks = 7 even passes)
#define XROWS_MAX 36         // HA + KH - 1
#define NSAMP 1024           // 4 * 16 * 16
#define SAMP_ELEMS (IC*NTAU*NAP)          // 34816 floats per sample
#define XMAX_ELEMS (IC*XROWS_MAX*NAP)     // 19584 floats worst-case half tile
#define WELEMS (IC*KH*KW*OC)              // 6400
#define KVOL (IC*KH*KW)                   // 200

typedef unsigned long long u64;

// ---------------- device scratch (no allocations allowed) ----------------
__device__ float g_xT[NSAMP * SAMP_ELEMS];   // ~142.6 MB transposed+padded input
__device__ float g_w[WELEMS];                // normalized weights [c][kh][kw][oc]
__device__ u64   g_key[2 * NSAMP * OC];      // per-half ordered argmax keys

// ---------------- packed f32x2 helpers (Blackwell FFMA2) ----------------
__device__ __forceinline__ u64 pack_dup(float v) {
    u64 r; asm("mov.b64 %0, {%1, %1};" : "=l"(r) : "f"(v)); return r;
}
__device__ __forceinline__ void unpack2(u64 v, float& lo, float& hi) {
    asm("mov.b64 {%0, %1}, %2;" : "=f"(lo), "=f"(hi) : "l"(v));
}
__device__ __forceinline__ u64 ffma2(u64 a, u64 b, u64 c) {
    u64 d; asm("fma.rn.f32x2 %0, %1, %2, %3;" : "=l"(d) : "l"(a), "l"(b), "l"(c));
    return d;
}

// ---------------- cp.async helpers ----------------
__device__ __forceinline__ unsigned smem_u32(const void* p) {
    return (unsigned)__cvta_generic_to_shared(p);
}
__device__ __forceinline__ void cp_async16(unsigned saddr, const void* gaddr) {
    asm volatile("cp.async.cg.shared.global [%0], [%1], 16;"
                 :: "r"(saddr), "l"(gaddr) : "memory");
}
__device__ __forceinline__ void cp_async_commit_wait() {
    asm volatile("cp.async.commit_group;\n\tcp.async.wait_group 0;" ::: "memory");
}

// ---------------- weight normalization (parallel) ----------------
// block = 256: each warp computes norms for 4 ocs, then coalesced scatter
__global__ void prep_weights_kernel(const float* __restrict__ v,
                                    const float* __restrict__ g) {
    __shared__ float scale[OC];
    int tid = threadIdx.x;
    int warp = tid >> 5, lane = tid & 31;

    #pragma unroll
    for (int j = 0; j < 4; j++) {
        int oc = warp * 4 + j;
        const float* vp = v + oc * KVOL;
        float s = 0.0f;
        for (int i = lane; i < KVOL; i += 32) { float t = vp[i]; s += t * t; }
        #pragma unroll
        for (int o = 16; o > 0; o >>= 1) s += __shfl_down_sync(0xFFFFFFFFu, s, o);
        if (lane == 0) scale[oc] = g[oc] / sqrtf(s);
    }
    __syncthreads();

    // g_w[r*OC + oc] = v[oc*KVOL + r] * scale[oc], r = (c*KH+kh)*KW+kw
    for (int i = tid; i < WELEMS; i += 256) {
        int oc = i & 31;
        int r  = i >> 5;
        g_w[i] = v[oc * KVOL + r] * scale[oc];
    }
}

// ---------------- transpose (B,C,T,A,P) -> xT[n][c][t][a68], n=b*256+p ----------------
// grid = 2048 (one per (b,c,t)), block = 256, dyn smem = 256*69*4 B
__global__ void transpose_kernel(const float* __restrict__ x) {
    extern __shared__ float tile[];        // [256][69] padded (stride 69 -> conflict-free)
    int bct = blockIdx.x;                  // (b*8 + c)*64 + t
    int b = bct >> 9;
    int c = (bct >> 6) & 7;
    int t = bct & 63;
    int tid = threadIdx.x;

    const float* src = x + (size_t)bct * (NANG * 256);
    for (int a = 0; a < NANG; a++)
        tile[tid * 69 + a] = src[a * 256 + tid];
    __syncthreads();

    int warp = tid >> 5, lane = tid & 31;
    for (int rr = 0; rr < 32; rr++) {
        int p = warp * 32 + rr;
        int n = b * 256 + p;
        int base = ((n * IC + c) * NTAU + t) * NAP;
        #pragma unroll
        for (int j = 0; j < 3; j++) {
            int a = j * 32 + lane;
            if (a < NAP) g_xT[base + a] = tile[p * 69 + (a & 63)]; // wrap for a>=64
        }
    }
}

// ---------------- conv + per-(n,oc,half) max/argmax ----------------
// grid = (1024, 2): one (sample, h-half) per CTA; block = 256
// dyn smem <= (XMAX_ELEMS + WELEMS)*4 = 101.5 KB -> 2 CTAs/SM, 16 warps/SM
__global__ void __launch_bounds__(256, 2) conv_kernel() {
    extern __shared__ float smem[];
    float* sx = smem;                    // [IC][xrows][NAP]
    __shared__ u64 best[OC];

    int n      = blockIdx.x;
    int half   = blockIdx.y;
    int h0     = half ? HA : 0;
    int hcount = half ? HB : HA;         // 28 or 32
    int xrows  = hcount + KH - 1;        // 32 or 36
    int tid    = threadIdx.x;

    float* sw = smem + IC * xrows * NAP; // [c][kh][kw][oc]

    // cooperative async loads: xrows contiguous rows per channel (16B aligned)
    {
        int rowf4 = xrows * NAP / 4;     // float4 per channel slab
        for (int c = 0; c < IC; c++) {
            const float4* s4 = (const float4*)(g_xT + (size_t)n * SAMP_ELEMS
                                               + (c * NTAU + h0) * NAP);
            float4* d4 = (float4*)(sx + c * xrows * NAP);
            #pragma unroll 1
            for (int i = tid; i < rowf4; i += 256)
                cp_async16(smem_u32(d4 + i), s4 + i);
        }
        const float4* w4 = (const float4*)g_w;
        #pragma unroll 1
        for (int i = tid; i < WELEMS / 4; i += 256)
            cp_async16(smem_u32((float4*)sw + i), w4 + i);
        if (tid < OC) best[tid] = 0ull;
        cp_async_commit_wait();
    }
    __syncthreads();

    int warp   = tid >> 5;       // 0..7, owns 4 ocs
    int ocbase = warp * 4;
    int lane   = tid & 31;

    u64 lb[4];
    #pragma unroll
    for (int i = 0; i < 4; i++) lb[i] = 0ull;

    // tasks: hcount*8 (256 or 224) -> exactly 8 or 7 full passes per lane
    for (int task = lane; task < hcount * 8; task += 32) {
        int lh = task >> 3;
        int wg = task & 7;

        // acc[j][ww]: packed pair (oc = ocbase + 2j, 2j+1) at output col wg*8+ww
        u64 acc[2][8];
        #pragma unroll
        for (int j = 0; j < 2; j++)
            #pragma unroll
            for (int ww = 0; ww < 8; ww++) acc[j][ww] = 0ull;

        #pragma unroll 1
        for (int c = 0; c < IC; c++) {
            const float* xc = sx + (c * xrows + lh) * NAP + wg * 8;
            const u64*   wc = (const u64*)(sw + c * KH * KW * OC + ocbase);
            #pragma unroll
            for (int kh = 0; kh < KH; kh++) {
                const float* xr = xc + kh * NAP;
                float4 x0 = *(const float4*)(xr);
                float4 x1 = *(const float4*)(xr + 4);
                float4 x2 = *(const float4*)(xr + 8);
                float xv[12] = {x0.x,x0.y,x0.z,x0.w, x1.x,x1.y,x1.z,x1.w,
                                x2.x,x2.y,x2.z,x2.w};
                u64 xp[12];
                #pragma unroll
                for (int k = 0; k < 12; k++) xp[k] = pack_dup(xv[k]);

                const u64* wr = wc + kh * (KW * OC / 2);
                #pragma unroll
                for (int kw = 0; kw < KW; kw++) {
                    u64 w0 = wr[kw * 16 + 0];
                    u64 w1 = wr[kw * 16 + 1];
                    #pragma unroll
                    for (int ww = 0; ww < 8; ww++) {
                        u64 xb = xp[ww + kw];
                        acc[0][ww] = ffma2(w0, xb, acc[0][ww]);
                        acc[1][ww] = ffma2(w1, xb, acc[1][ww]);
                    }
                }
            }
        }

        // fold into ordered-key argmax (tie-break: smaller flat index wins)
        int hglob = h0 + lh;
        #pragma unroll
        for (int j = 0; j < 2; j++) {
            #pragma unroll
            for (int ww = 0; ww < 8; ww++) {
                float v0, v1;
                unpack2(acc[j][ww], v0, v1);
                int idx = hglob * NANG + wg * 8 + ww;
                unsigned ir = 0xFFFFFFFFu - (unsigned)idx;
                unsigned a0 = __float_as_uint(v0);
                a0 = (a0 & 0x80000000u) ? ~a0 : (a0 | 0x80000000u);
                u64 k0 = ((u64)a0 << 32) | ir;
                if (k0 > lb[2*j])   lb[2*j]   = k0;
                unsigned a1 = __float_as_uint(v1);
                a1 = (a1 & 0x80000000u) ? ~a1 : (a1 | 0x80000000u);
                u64 k1 = ((u64)a1 << 32) | ir;
                if (k1 > lb[2*j+1]) lb[2*j+1] = k1;
            }
        }
    }

    // warp-level max-reduce (all lanes share the same 4 ocs), lane 0 stores
    #pragma unroll
    for (int i = 0; i < 4; i++) {
        #pragma unroll
        for (int o = 16; o > 0; o >>= 1) {
            u64 other = __shfl_down_sync(0xFFFFFFFFu, lb[i], o);
            if (other > lb[i]) lb[i] = other;
        }
    }
    if (lane == 0) {
        #pragma unroll
        for (int i = 0; i < 4; i++) best[ocbase + i] = lb[i];
    }
    __syncthreads();

    if (tid < OC)
        g_key[(size_t)half * (NSAMP * OC) + n * OC + tid] = best[tid];
}

// ---------------- block reductions (256 threads) ----------------
__device__ __forceinline__ float blk_sum(float v, float* sbuf) {
    #pragma unroll
    for (int o = 16; o > 0; o >>= 1) v += __shfl_down_sync(0xFFFFFFFFu, v, o);
    int w = threadIdx.x >> 5, l = threadIdx.x & 31;
    if (l == 0) sbuf[w] = v;
    __syncthreads();
    if (w == 0) {
        float t = (l < 8) ? sbuf[l] : 0.0f;
        #pragma unroll
        for (int o = 4; o > 0; o >>= 1) t += __shfl_down_sync(0xFFFFFFFFu, t, o);
        if (l == 0) sbuf[8] = t;
    }
    __syncthreads();
    float r = sbuf[8];
    __syncthreads();
    return r;
}

__device__ __forceinline__ float blk_max(float v, float* sbuf) {
    #pragma unroll
    for (int o = 16; o > 0; o >>= 1)
        v = fmaxf(v, __shfl_down_sync(0xFFFFFFFFu, v, o));
    int w = threadIdx.x >> 5, l = threadIdx.x & 31;
    if (l == 0) sbuf[w] = v;
    __syncthreads();
    if (w == 0) {
        float t = (l < 8) ? sbuf[l] : -3.4e38f;
        #pragma unroll
        for (int o = 4; o > 0; o >>= 1)
            t = fmaxf(t, __shfl_down_sync(0xFFFFFFFFu, t, o));
        if (l == 0) sbuf[8] = t;
    }
    __syncthreads();
    float r = sbuf[8];
    __syncthreads();
    return r;
}

// ---------------- merge halves + softmax over spatial + phase encoding ----------------
// grid = (OC, 4), block = 256 (one thread per spatial position)
__global__ void finalize_kernel(float* __restrict__ out) {
    __shared__ float sbuf[9];
    int oc = blockIdx.x;
    int b  = blockIdx.y;
    int p  = threadIdx.x;
    int n  = b * 256 + p;

    u64 k0 = g_key[n * OC + oc];
    u64 k1 = g_key[(size_t)NSAMP * OC + n * OC + oc];
    u64 k  = (k1 > k0) ? k1 : k0;

    unsigned u = (unsigned)(k >> 32);
    unsigned bits = (u & 0x80000000u) ? (u ^ 0x80000000u) : ~u;
    float v  = __uint_as_float(bits);
    int   id = (int)(0xFFFFFFFFu - (unsigned)(k & 0xFFFFFFFFu));

    float m = blk_max(v, sbuf);
    float e = expf(v - m);
    float s = blk_sum(e, sbuf);
    float w = e / s;

    float tau = ((float)id / 64.0f) / 64.0f;      // (idx / NA) / NT, true division
    float mt  = blk_sum(w * tau, sbuf);

    float th = (float)(id & 63);
    float ph = (6.28318530717958647692f * th) / 64.0f;
    float mc = blk_sum(w * cosf(ph), sbuf);
    float ms = blk_sum(w * sinf(ph), sbuf);
    float ang = atan2f(ms, mc);
    float rel = ph - ang;

    int base = (b * 256 + p) * (4 * OC);
    out[base + oc]          = v;
    out[base + OC + oc]     = tau - mt;
    out[base + 2*OC + oc]   = cosf(rel);
    out[base + 3*OC + oc]   = sinf(rel);
}

// ---------------- launch ----------------
extern "C" void kernel_launch(void* const* d_in, const int* in_sizes, int n_in,
                              void* d_out, int out_size) {
    const float* x  = (const float*)d_in[0];   // (4,8,64,64,16,16)
    const float* cv = (const float*)d_in[1];   // (32,8,5,5)
    const float* cg = (const float*)d_in[2];   // (32,)
    float* out = (float*)d_out;                // (4,16,16,128,1,1)

    cudaFuncSetAttribute(transpose_kernel,
                         cudaFuncAttributeMaxDynamicSharedMemorySize, 256*69*4);
    cudaFuncSetAttribute(conv_kernel,
                         cudaFuncAttributeMaxDynamicSharedMemorySize,
                         (XMAX_ELEMS + WELEMS) * 4);

    prep_weights_kernel<<<1, 256>>>(cv, cg);
    transpose_kernel<<<2048, 256, 256*69*4>>>(x);
    dim3 cg2(NSAMP, 2);
    conv_kernel<<<cg2, 256, (XMAX_ELEMS + WELEMS) * 4>>>();
    dim3 fg(OC, 4);
    finalize_kernel<<<fg, 256>>>(out);
}

// round 15
// speedup vs baseline: 1.3341x; 1.1080x over previous
#include <cuda_runtime.h>
#include <math.h>

// ---------------- problem constants ----------------
#define NTAU 64
#define NANG 64
#define NAP  68              // NANG + KW-1 circular pad
#define IC   8
#define OC   32
#define KH   5
#define KW   5
#define NTAPS 25
#define NSAMP 1024           // 4 * 16 * 16
#define SAMP_ELEMS (IC*NTAU*NAP)      // 34816 floats per sample
#define KVOL 200
#define NCHUNK 4             // h-chunks: 16,16,16,12 rows
#define PLANE 1384           // padded smem channel stride (floats): ≡8 mod 32, mult of 4
#define XS_ELEMS (IC*PLANE)            // 11072 floats = 44288 B
#define WPK_ELEMS (NTAPS*OC*4*4)       // 12800 floats = 51200 B (packed hi/lo frags)
#define CONV_SMEM ((XS_ELEMS + WPK_ELEMS)*4)   // 95488 B

typedef unsigned long long u64;

// ---------------- device scratch (no allocations allowed) ----------------
__device__ float g_xT[NSAMP * SAMP_ELEMS];   // transposed+padded input
__device__ float g_wpk[WPK_ELEMS];           // packed tf32-split weights
__device__ u64   g_key[NCHUNK * NSAMP * OC]; // per-chunk ordered argmax keys

// ---------------- helpers ----------------
__device__ __forceinline__ unsigned smem_u32(const void* p) {
    return (unsigned)__cvta_generic_to_shared(p);
}
__device__ __forceinline__ void cp_async16(unsigned saddr, const void* gaddr) {
    asm volatile("cp.async.cg.shared.global [%0], [%1], 16;"
                 :: "r"(saddr), "l"(gaddr) : "memory");
}
__device__ __forceinline__ void cp_async_commit_wait() {
    asm volatile("cp.async.commit_group;\n\tcp.async.wait_group 0;" ::: "memory");
}
__device__ __forceinline__ unsigned f2tf32(float x) {
    unsigned r; asm("cvt.rna.tf32.f32 %0, %1;" : "=r"(r) : "f"(x)); return r;
}
__device__ __forceinline__ void mma_tf32(float* d,
        unsigned a0, unsigned a1, unsigned a2, unsigned a3,
        unsigned b0, unsigned b1) {
    asm volatile("mma.sync.aligned.m16n8k8.row.col.f32.tf32.tf32.f32 "
        "{%0,%1,%2,%3}, {%4,%5,%6,%7}, {%8,%9}, {%0,%1,%2,%3};"
        : "+f"(d[0]), "+f"(d[1]), "+f"(d[2]), "+f"(d[3])
        : "r"(a0), "r"(a1), "r"(a2), "r"(a3), "r"(b0), "r"(b1));
}

// ---------------- weight normalization + tf32 split packing ----------------
// g_wpk[((tap*32 + oc)*4 + t4)*4 + {hi_k=t4, hi_k=t4+4, lo_k=t4, lo_k=t4+4}]
__global__ void prep_weights_kernel(const float* __restrict__ v,
                                    const float* __restrict__ g) {
    __shared__ float scale[OC];
    int tid = threadIdx.x;
    int warp = tid >> 5, lane = tid & 31;

    #pragma unroll
    for (int j = 0; j < 4; j++) {
        int oc = warp * 4 + j;
        const float* vp = v + oc * KVOL;
        float s = 0.0f;
        for (int i = lane; i < KVOL; i += 32) { float t = vp[i]; s += t * t; }
        #pragma unroll
        for (int o = 16; o > 0; o >>= 1) s += __shfl_down_sync(0xFFFFFFFFu, s, o);
        if (lane == 0) scale[oc] = g[oc] / sqrtf(s);
    }
    __syncthreads();

    for (int i = tid; i < NTAPS * OC * 4; i += 256) {
        int tap = i >> 7;            // 128 slots per tap
        int n   = (i >> 2) & 31;
        int t4  = i & 3;
        float sc = scale[n];
        float v0 = v[n * KVOL + t4 * NTAPS + tap] * sc;        // k = t4
        float v1 = v[n * KVOL + (t4 + 4) * NTAPS + tap] * sc;  // k = t4+4
        unsigned h0 = f2tf32(v0), h1 = f2tf32(v1);
        unsigned l0 = f2tf32(v0 - __uint_as_float(h0));
        unsigned l1 = f2tf32(v1 - __uint_as_float(h1));
        float4* dst = (float4*)(g_wpk + i * 4);
        *dst = make_float4(__uint_as_float(h0), __uint_as_float(h1),
                           __uint_as_float(l0), __uint_as_float(l1));
    }
}

// ---------------- transpose (B,C,T,A,P) -> xT[n][c][t][a68], n=b*256+p ----------------
__global__ void transpose_kernel(const float* __restrict__ x) {
    extern __shared__ float tile[];        // [256][69]
    int bct = blockIdx.x;                  // (b*8 + c)*64 + t
    int b = bct >> 9;
    int c = (bct >> 6) & 7;
    int t = bct & 63;
    int tid = threadIdx.x;

    const float* src = x + (size_t)bct * (NANG * 256);
    for (int a = 0; a < NANG; a++)
        tile[tid * 69 + a] = src[a * 256 + tid];
    __syncthreads();

    int warp = tid >> 5, lane = tid & 31;
    for (int rr = 0; rr < 32; rr++) {
        int p = warp * 32 + rr;
        int n = b * 256 + p;
        int base = ((n * IC + c) * NTAU + t) * NAP;
        #pragma unroll
        for (int j = 0; j < 3; j++) {
            int a = j * 32 + lane;
            if (a < NAP) g_xT[base + a] = tile[p * 69 + (a & 63)]; // wrap for a>=64
        }
    }
}

// ---------------- implicit-GEMM conv (mma.sync tf32 x3) + argmax ----------------
// grid = (1024, 4): (sample, h-chunk); block = 256; smem 95.5 KB -> 2 CTAs/SM
__global__ void __launch_bounds__(256, 2) conv_kernel() {
    extern __shared__ float smem[];
    float* sx  = smem;                // [IC][PLANE]
    float* swp = smem + XS_ELEMS;     // packed W frags
    __shared__ u64 best[OC];

    int n     = blockIdx.x;
    int chunk = blockIdx.y;
    int h0     = chunk * 16;
    int hcount = (chunk == 3) ? 12 : 16;
    int xrows  = hcount + KH - 1;     // 20 or 16
    int tid = threadIdx.x;
    int warp = tid >> 5, lane = tid & 31;
    int g = lane >> 2, t4 = lane & 3;

    // cooperative async loads
    {
        int nf4 = xrows * (NAP / 4);  // 17 float4 per row, rows contiguous
        for (int c = 0; c < IC; c++) {
            const float4* s4 = (const float4*)(g_xT + (size_t)n * SAMP_ELEMS
                                               + (c * NTAU + h0) * NAP);
            float4* d4 = (float4*)(sx + c * PLANE);
            #pragma unroll 1
            for (int i = tid; i < nf4; i += 256)
                cp_async16(smem_u32(d4 + i), s4 + i);
        }
        const float4* w4 = (const float4*)g_wpk;
        #pragma unroll 1
        for (int i = tid; i < WPK_ELEMS / 4; i += 256)
            cp_async16(smem_u32((float4*)swp + i), w4 + i);
        if (tid < OC) best[tid] = 0ull;
        cp_async_commit_wait();
    }
    __syncthreads();

    u64 lb[8];                        // keys for ocs nt*8 + 2*t4 + j
    #pragma unroll
    for (int i = 0; i < 8; i++) lb[i] = 0ull;

    int mtiles = hcount * 4;          // 64 or 48 (16-wide theta tiles)
    int mpw = mtiles >> 3;            // 8 or 6 per warp
    const uint4* wq = (const uint4*)swp;

    for (int im = 0; im < mpw; im++) {
        int mt = warp * mpw + im;
        int lh = mt >> 2;             // local h row
        int ab = (mt & 3) * 16;       // theta base
        const float* px = sx + t4 * PLANE + lh * NAP + ab + g;

        float D[16];
        #pragma unroll
        for (int i = 0; i < 16; i++) D[i] = 0.0f;

        #pragma unroll 1
        for (int kh = 0; kh < KH; kh++) {
            #pragma unroll
            for (int kw = 0; kw < KW; kw++) {
                int off = kh * NAP + kw;
                float f0 = px[off];
                float f1 = px[off + 8];
                float f2 = px[4 * PLANE + off];
                float f3 = px[4 * PLANE + off + 8];
                unsigned ah0 = f2tf32(f0), ah1 = f2tf32(f1);
                unsigned ah2 = f2tf32(f2), ah3 = f2tf32(f3);
                unsigned al0 = f2tf32(f0 - __uint_as_float(ah0));
                unsigned al1 = f2tf32(f1 - __uint_as_float(ah1));
                unsigned al2 = f2tf32(f2 - __uint_as_float(ah2));
                unsigned al3 = f2tf32(f3 - __uint_as_float(ah3));
                int tap = kh * KW + kw;
                #pragma unroll
                for (int nt = 0; nt < 4; nt++) {
                    uint4 b = wq[tap * 128 + (nt * 8 + g) * 4 + t4];
                    // b.x=hi(k=t4) b.y=hi(k=t4+4) b.z=lo(k=t4) b.w=lo(k=t4+4)
                    mma_tf32(D + nt * 4, ah0, ah1, ah2, ah3, b.x, b.y); // Ahi*Bhi
                    mma_tf32(D + nt * 4, ah0, ah1, ah2, ah3, b.z, b.w); // Ahi*Blo
                    mma_tf32(D + nt * 4, al0, al1, al2, al3, b.x, b.y); // Alo*Bhi
                }
            }
        }

        // fold into ordered-key argmax (tie-break: smaller flat index wins)
        int hg = h0 + lh;
        #pragma unroll
        for (int nt = 0; nt < 4; nt++) {
            #pragma unroll
            for (int j = 0; j < 4; j++) {
                int theta = ab + g + ((j >> 1) << 3);
                int idx = hg * NANG + theta;
                unsigned a = __float_as_uint(D[nt * 4 + j]);
                a = (a & 0x80000000u) ? ~a : (a | 0x80000000u);
                u64 k = ((u64)a << 32) | (unsigned)(0xFFFFFFFFu - idx);
                int li = nt * 2 + (j & 1);
                if (k > lb[li]) lb[li] = k;
            }
        }
    }

    // reduce over lanes sharing t4 (g varies): offsets 16, 8, 4
    #pragma unroll
    for (int i = 0; i < 8; i++) {
        #pragma unroll
        for (int o = 16; o >= 4; o >>= 1) {
            u64 other = __shfl_down_sync(0xFFFFFFFFu, lb[i], o);
            if (other > lb[i]) lb[i] = other;
        }
    }
    if (g == 0) {                     // lanes 0..3 hold reduced keys
        #pragma unroll
        for (int nt = 0; nt < 4; nt++) {
            atomicMax(&best[nt * 8 + t4 * 2 + 0], lb[nt * 2 + 0]);
            atomicMax(&best[nt * 8 + t4 * 2 + 1], lb[nt * 2 + 1]);
        }
    }
    __syncthreads();

    if (tid < OC)
        g_key[((size_t)chunk * NSAMP + n) * OC + tid] = best[tid];
}

// ---------------- block reductions (256 threads) ----------------
__device__ __forceinline__ float blk_sum(float v, float* sbuf) {
    #pragma unroll
    for (int o = 16; o > 0; o >>= 1) v += __shfl_down_sync(0xFFFFFFFFu, v, o);
    int w = threadIdx.x >> 5, l = threadIdx.x & 31;
    if (l == 0) sbuf[w] = v;
    __syncthreads();
    if (w == 0) {
        float t = (l < 8) ? sbuf[l] : 0.0f;
        #pragma unroll
        for (int o = 4; o > 0; o >>= 1) t += __shfl_down_sync(0xFFFFFFFFu, t, o);
        if (l == 0) sbuf[8] = t;
    }
    __syncthreads();
    float r = sbuf[8];
    __syncthreads();
    return r;
}

__device__ __forceinline__ float blk_max(float v, float* sbuf) {
    #pragma unroll
    for (int o = 16; o > 0; o >>= 1)
        v = fmaxf(v, __shfl_down_sync(0xFFFFFFFFu, v, o));
    int w = threadIdx.x >> 5, l = threadIdx.x & 31;
    if (l == 0) sbuf[w] = v;
    __syncthreads();
    if (w == 0) {
        float t = (l < 8) ? sbuf[l] : -3.4e38f;
        #pragma unroll
        for (int o = 4; o > 0; o >>= 1)
            t = fmaxf(t, __shfl_down_sync(0xFFFFFFFFu, t, o));
        if (l == 0) sbuf[8] = t;
    }
    __syncthreads();
    float r = sbuf[8];
    __syncthreads();
    return r;
}

// ---------------- merge chunks + softmax over spatial + phase encoding ----------------
// grid = (OC, 4), block = 256 (one thread per spatial position)
__global__ void finalize_kernel(float* __restrict__ out) {
    __shared__ float sbuf[9];
    int oc = blockIdx.x;
    int b  = blockIdx.y;
    int p  = threadIdx.x;
    int n  = b * 256 + p;

    u64 k = g_key[(size_t)n * OC + oc];
    #pragma unroll
    for (int c = 1; c < NCHUNK; c++) {
        u64 kc = g_key[((size_t)c * NSAMP + n) * OC + oc];
        if (kc > k) k = kc;
    }

    unsigned u = (unsigned)(k >> 32);
    unsigned bits = (u & 0x80000000u) ? (u ^ 0x80000000u) : ~u;
    float v  = __uint_as_float(bits);
    int   id = (int)(0xFFFFFFFFu - (unsigned)(k & 0xFFFFFFFFu));

    float m = blk_max(v, sbuf);
    float e = expf(v - m);
    float s = blk_sum(e, sbuf);
    float w = e / s;

    float tau = ((float)id / 64.0f) / 64.0f;      // (idx / NA) / NT, true division
    float mt  = blk_sum(w * tau, sbuf);

    float th = (float)(id & 63);
    float ph = (6.28318530717958647692f * th) / 64.0f;
    float mc = blk_sum(w * cosf(ph), sbuf);
    float ms = blk_sum(w * sinf(ph), sbuf);
    float ang = atan2f(ms, mc);
    float rel = ph - ang;

    int base = (b * 256 + p) * (4 * OC);
    out[base + oc]          = v;
    out[base + OC + oc]     = tau - mt;
    out[base + 2*OC + oc]   = cosf(rel);
    out[base + 3*OC + oc]   = sinf(rel);
}

// ---------------- launch ----------------
extern "C" void kernel_launch(void* const* d_in, const int* in_sizes, int n_in,
                              void* d_out, int out_size) {
    const float* x  = (const float*)d_in[0];   // (4,8,64,64,16,16)
    const float* cv = (const float*)d_in[1];   // (32,8,5,5)
    const float* cg = (const float*)d_in[2];   // (32,)
    float* out = (float*)d_out;                // (4,16,16,128,1,1)

    cudaFuncSetAttribute(transpose_kernel,
                         cudaFuncAttributeMaxDynamicSharedMemorySize, 256*69*4);
    cudaFuncSetAttribute(conv_kernel,
                         cudaFuncAttributeMaxDynamicSharedMemorySize, CONV_SMEM);

    prep_weights_kernel<<<1, 256>>>(cv, cg);
    transpose_kernel<<<2048, 256, 256*69*4>>>(x);
    dim3 cgrid(NSAMP, NCHUNK);
    conv_kernel<<<cgrid, 256, CONV_SMEM>>>();
    dim3 fg(OC, 4);
    finalize_kernel<<<fg, 256>>>(out);
}